// round 1
// baseline (speedup 1.0000x reference)
#include <cuda_runtime.h>

#define NB   2
#define NC   256
#define NPIX 4096
#define CI   128
#define EPSV 1e-5f

// ---------------- scratch (device globals; no allocation allowed) ------------
__device__ float g_A [(size_t)NB * NPIX * NPIX];   // affinity logits, 134 MB
__device__ float g_VQ[(size_t)NB * NPIX * CI];     // v(q), pixel-major [n][c]
__device__ float g_VS[(size_t)NB * NPIX * CI];     // v(s)
__device__ float g_KT[(size_t)NB * NPIX * CI];     // k_x^T  [n][c]
__device__ float g_QT[(size_t)NB * NPIX * CI];     // q_x^T  [m][c]
__device__ float g_ST[(size_t)NB * CI * NPIX];     // bn(conv_ts(s)) chan-major
__device__ float g_TQ[(size_t)NB * CI * NPIX];     // bn(conv_tq(q)) chan-major
__device__ float g_rowmax[NB * NPIX];
__device__ float g_rowsum[NB * NPIX];
__device__ float g_colpm [NB * 8 * NPIX];
__device__ float g_colps [NB * 8 * NPIX];
__device__ float g_colmax[NB * NPIX];
__device__ float g_colsum[NB * NPIX];

// conv1x1 destination selector (resolved in device code; avoids symbol-address APIs)
__device__ __forceinline__ float* conv_dst(int dst) {
    switch (dst) {
        case 0: return g_VQ;
        case 1: return g_VS;
        case 2: return g_KT;
        case 3: return g_QT;
        case 4: return g_ST;
        default: return g_TQ;
    }
}

// ---------------- conv1x1 (+optional BN), tiled GEMM W[OC,256] @ X[256,4096] --
template<int OC, bool CHAN_MAJOR>
__global__ __launch_bounds__(256) void conv1x1_kernel(
    const float* __restrict__ X,     // [NB][256][NPIX]
    const float* __restrict__ W,     // [OC][256]
    const float* __restrict__ bias,  // [OC]
    const float* __restrict__ bng, const float* __restrict__ bnb,
    const float* __restrict__ bnm, const float* __restrict__ bnv,
    int dst, int out_off)
{
    const int b  = blockIdx.y;
    const int n0 = blockIdx.x * 128;
    const float* Xb = X + (size_t)b * NC * NPIX;
    float* out = conv_dst(dst);

    __shared__ float Ws[16][OC];
    __shared__ float Xs[16][128];
    constexpr int RPT = OC / 16;   // 8 or 4 rows per thread
    float acc[RPT][8];
    #pragma unroll
    for (int i = 0; i < RPT; i++)
        #pragma unroll
        for (int j = 0; j < 8; j++) acc[i][j] = 0.f;

    const int t  = threadIdx.x;
    const int rg = t >> 4, cg = t & 15;

    for (int k0 = 0; k0 < NC; k0 += 16) {
        for (int i = t; i < OC * 16; i += 256) {
            int oc = i >> 4, kk = i & 15;
            Ws[kk][oc] = W[oc * NC + k0 + kk];
        }
        for (int i = t; i < 16 * 128; i += 256) {
            int kk = i >> 7, px = i & 127;
            Xs[kk][px] = Xb[(size_t)(k0 + kk) * NPIX + n0 + px];
        }
        __syncthreads();
        #pragma unroll
        for (int kk = 0; kk < 16; kk++) {
            float a[RPT], xv[8];
            #pragma unroll
            for (int i = 0; i < RPT; i++) a[i] = Ws[kk][rg * RPT + i];
            #pragma unroll
            for (int j = 0; j < 8; j++) xv[j] = Xs[kk][cg * 8 + j];
            #pragma unroll
            for (int i = 0; i < RPT; i++)
                #pragma unroll
                for (int j = 0; j < 8; j++) acc[i][j] += a[i] * xv[j];
        }
        __syncthreads();
    }

    #pragma unroll
    for (int i = 0; i < RPT; i++) {
        int oc = rg * RPT + i;
        float sc = 1.f, off = bias[oc];
        if (CHAN_MAJOR) {                      // fused BN
            float inv = bng[oc] * rsqrtf(bnv[oc] + EPSV);
            sc  = inv;
            off = (bias[oc] - bnm[oc]) * inv + bnb[oc];
        }
        #pragma unroll
        for (int j = 0; j < 8; j++) {
            int px = cg * 8 + j;
            float v = acc[i][j] * sc + off;
            if (CHAN_MAJOR)
                out[((size_t)b * CI + oc) * NPIX + n0 + px] = v;
            else
                out[((size_t)b * NPIX + n0 + px) * CI + out_off + oc] = v;
        }
    }
}

// ---------------- A[n][m] = dot(KT[n], QT[m])  (NT GEMM, K=128) --------------
__global__ __launch_bounds__(256) void gemmA_kernel()
{
    const int b  = blockIdx.z;
    const int m0 = blockIdx.x * 128;
    const int n0 = blockIdx.y * 128;
    const float* Kp = g_KT + (size_t)b * NPIX * CI;
    const float* Qp = g_QT + (size_t)b * NPIX * CI;

    __shared__ float Ks[16][132];
    __shared__ float Qs[16][132];
    float acc[8][8] = {};
    const int t  = threadIdx.x;
    const int rg = t >> 4, cg = t & 15;

    for (int k0 = 0; k0 < CI; k0 += 16) {
        for (int i = t; i < 128 * 16; i += 256) {
            int row = i >> 4, kk = i & 15;
            Ks[kk][row] = Kp[(size_t)(n0 + row) * CI + k0 + kk];
            Qs[kk][row] = Qp[(size_t)(m0 + row) * CI + k0 + kk];
        }
        __syncthreads();
        #pragma unroll
        for (int kk = 0; kk < 16; kk++) {
            float a[8], q[8];
            #pragma unroll
            for (int i = 0; i < 8; i++) a[i] = Ks[kk][rg * 8 + i];
            #pragma unroll
            for (int j = 0; j < 8; j++) q[j] = Qs[kk][cg * 8 + j];
            #pragma unroll
            for (int i = 0; i < 8; i++)
                #pragma unroll
                for (int j = 0; j < 8; j++) acc[i][j] += a[i] * q[j];
        }
        __syncthreads();
    }
    float* Ab = g_A + (size_t)b * NPIX * NPIX;
    #pragma unroll
    for (int i = 0; i < 8; i++)
        #pragma unroll
        for (int j = 0; j < 8; j++)
            Ab[(size_t)(n0 + rg * 8 + i) * NPIX + m0 + cg * 8 + j] = acc[i][j];
}

// ---------------- softmax stats (online max/sum) -----------------------------
__global__ __launch_bounds__(256) void rowstats_kernel()
{
    const int b = blockIdx.y, n = blockIdx.x, t = threadIdx.x;
    const float* row = g_A + ((size_t)b * NPIX + n) * NPIX;
    float m = -1e30f, s = 0.f;
    for (int j = t; j < NPIX; j += 256) {
        float x = row[j];
        if (x > m) { s *= __expf(m - x); m = x; }
        s += __expf(x - m);
    }
    __shared__ float sm_[256], ss_[256];
    sm_[t] = m; ss_[t] = s;
    __syncthreads();
    for (int st = 128; st > 0; st >>= 1) {
        if (t < st) {
            float m2 = sm_[t + st], s2 = ss_[t + st];
            float M = fmaxf(sm_[t], m2);
            ss_[t] = ss_[t] * __expf(sm_[t] - M) + s2 * __expf(m2 - M);
            sm_[t] = M;
        }
        __syncthreads();
    }
    if (t == 0) { g_rowmax[b * NPIX + n] = sm_[0]; g_rowsum[b * NPIX + n] = ss_[0]; }
}

__global__ __launch_bounds__(256) void colstats_partial_kernel()
{
    const int b   = blockIdx.z;
    const int col = blockIdx.x * 256 + threadIdx.x;
    const int nc  = blockIdx.y;     // 0..7, 512 rows each
    const float* Ab = g_A + (size_t)b * NPIX * NPIX;
    float m = -1e30f, s = 0.f;
    const int nend = nc * 512 + 512;
    for (int n = nc * 512; n < nend; n++) {
        float x = Ab[(size_t)n * NPIX + col];
        if (x > m) { s *= __expf(m - x); m = x; }
        s += __expf(x - m);
    }
    g_colpm[((size_t)b * 8 + nc) * NPIX + col] = m;
    g_colps[((size_t)b * 8 + nc) * NPIX + col] = s;
}

__global__ __launch_bounds__(256) void colstats_combine_kernel()
{
    int idx = blockIdx.x * 256 + threadIdx.x;     // over NB*NPIX
    int b = idx / NPIX, col = idx % NPIX;
    float m = -1e30f, s = 0.f;
    for (int c = 0; c < 8; c++) {
        float m2 = g_colpm[((size_t)b * 8 + c) * NPIX + col];
        float s2 = g_colps[((size_t)b * 8 + c) * NPIX + col];
        float M = fmaxf(m, m2);
        s = s * __expf(m - M) + s2 * __expf(m2 - M);
        m = M;
    }
    g_colmax[idx] = m; g_colsum[idx] = s;
}

// ---------------- PV GEMM: E = scale * softmax(A) @ V / sum + T --------------
// mode 0: E_s (row softmax, V=v_s, T=s_t); mode 1: E_q (col softmax via A^T, V=v_q, T=q_t)
__global__ __launch_bounds__(256) void pv_kernel(
    const float* __restrict__ scale_p,
    float* __restrict__ out_eq, float* __restrict__ out_es)
{
    const int mode = blockIdx.z;
    const int b    = blockIdx.y;
    const int r0   = blockIdx.x * 128;
    const float* Ab = g_A + (size_t)b * NPIX * NPIX;
    const float* V  = (mode ? g_VQ : g_VS) + (size_t)b * NPIX * CI;
    const float* mx = (mode ? g_colmax : g_rowmax) + b * NPIX;
    const float* sm = (mode ? g_colsum : g_rowsum) + b * NPIX;
    const float* T  = (mode ? g_TQ : g_ST) + (size_t)b * CI * NPIX;
    float* out = (mode ? out_eq : out_es) + (size_t)b * CI * NPIX;
    const float scale = scale_p[0];

    __shared__ float As[16][132];
    __shared__ float Vs[16][132];
    __shared__ float rmx[128];
    const int t = threadIdx.x;
    if (t < 128) rmx[t] = mx[r0 + t];
    __syncthreads();

    float acc[8][8] = {};
    const int rg = t >> 4, cg = t & 15;

    for (int k0 = 0; k0 < NPIX; k0 += 16) {
        if (mode == 0) {
            for (int i = t; i < 128 * 16; i += 256) {
                int row = i >> 4, kk = i & 15;
                As[kk][row] = __expf(Ab[(size_t)(r0 + row) * NPIX + k0 + kk] - rmx[row]);
            }
        } else {
            for (int i = t; i < 128 * 16; i += 256) {
                int row = i & 127, kk = i >> 7;
                As[kk][row] = __expf(Ab[(size_t)(k0 + kk) * NPIX + r0 + row] - rmx[row]);
            }
        }
        for (int i = t; i < 16 * 128; i += 256) {
            int kk = i >> 7, c = i & 127;
            Vs[kk][c] = V[(size_t)(k0 + kk) * CI + c];
        }
        __syncthreads();
        #pragma unroll
        for (int kk = 0; kk < 16; kk++) {
            float a[8], v[8];
            #pragma unroll
            for (int i = 0; i < 8; i++) a[i] = As[kk][rg * 8 + i];
            #pragma unroll
            for (int j = 0; j < 8; j++) v[j] = Vs[kk][cg * 8 + j];
            #pragma unroll
            for (int i = 0; i < 8; i++)
                #pragma unroll
                for (int j = 0; j < 8; j++) acc[i][j] += a[i] * v[j];
        }
        __syncthreads();
    }

    #pragma unroll
    for (int i = 0; i < 8; i++) {
        int r = r0 + rg * 8 + i;
        float invs = scale / sm[r];
        #pragma unroll
        for (int j = 0; j < 8; j++) {
            int c = cg * 8 + j;
            out[(size_t)c * NPIX + r] = acc[i][j] * invs + T[(size_t)c * NPIX + r];
        }
    }
}

// ---------------- 3x3 conv (SAME) + BN + ReLU on cat(E_q, E_s) ---------------
__global__ __launch_bounds__(256) void conv3x3_kernel(
    const float* __restrict__ Wc,   // [128][256][3][3]
    const float* __restrict__ bng, const float* __restrict__ bnb,
    const float* __restrict__ bnm, const float* __restrict__ bnv,
    const float* __restrict__ Eq, const float* __restrict__ Es,
    float* __restrict__ outp)
{
    const int b = blockIdx.y;
    const int y = blockIdx.x;
    __shared__ float Xs[8][3][68];        // 8 ic, rows y-1..y+1, 66 cols (halo)
    __shared__ float Wsm[8][9][128];      // [ic][tap][oc]
    const int t   = threadIdx.x;
    const int pxg = t & 15, ocg = t >> 4;
    float acc[8][4] = {};

    for (int ic0 = 0; ic0 < 256; ic0 += 8) {
        const float* src = (ic0 < 128)
            ? Eq + ((size_t)b * CI + ic0) * NPIX
            : Es + ((size_t)b * CI + (ic0 - 128)) * NPIX;

        for (int i = t; i < 8 * 3 * 66; i += 256) {
            int ic = i / 198, rem = i - ic * 198;
            int dy = rem / 66, xx = rem - dy * 66;
            int xg = xx - 1, yg = y + dy - 1;
            float v = 0.f;
            if (xg >= 0 && xg < 64 && yg >= 0 && yg < 64)
                v = src[(size_t)ic * NPIX + yg * 64 + xg];
            Xs[ic][dy][xx] = v;
        }
        {
            int oc = t >> 1, half = t & 1;
            const float* wp = Wc + (size_t)oc * 2304 + (ic0 + half * 4) * 9;
            #pragma unroll
            for (int j = 0; j < 36; j++) {
                int icl = half * 4 + j / 9, tap = j - (j / 9) * 9;
                Wsm[icl][tap][oc] = wp[j];
            }
        }
        __syncthreads();

        #pragma unroll
        for (int ic = 0; ic < 8; ic++) {
            #pragma unroll
            for (int tap = 0; tap < 9; tap++) {
                const int dy = tap / 3, dx = tap - (tap / 3) * 3;
                float w[8], xv[4];
                #pragma unroll
                for (int o = 0; o < 8; o++) w[o] = Wsm[ic][tap][ocg * 8 + o];
                #pragma unroll
                for (int p = 0; p < 4; p++) xv[p] = Xs[ic][dy][pxg * 4 + p + dx];
                #pragma unroll
                for (int o = 0; o < 8; o++)
                    #pragma unroll
                    for (int p = 0; p < 4; p++) acc[o][p] += w[o] * xv[p];
            }
        }
        __syncthreads();
    }

    #pragma unroll
    for (int o = 0; o < 8; o++) {
        int oc = ocg * 8 + o;
        float inv = bng[oc] * rsqrtf(bnv[oc] + EPSV);
        float off = bnb[oc] - bnm[oc] * inv;
        #pragma unroll
        for (int p = 0; p < 4; p++) {
            int px = pxg * 4 + p;
            float v = acc[o][p] * inv + off;
            outp[((size_t)b * CI + oc) * NPIX + y * 64 + px] = fmaxf(v, 0.f);
        }
    }
}

// ---------------- launch ------------------------------------------------------
extern "C" void kernel_launch(void* const* d_in, const int* in_sizes, int n_in,
                              void* d_out, int out_size)
{
    (void)in_sizes; (void)n_in; (void)out_size;
    const float* q     = (const float*)d_in[0];
    const float* s     = (const float*)d_in[1];
    const float* scale = (const float*)d_in[2];
    const float* w_v   = (const float*)d_in[3];  const float* b_v  = (const float*)d_in[4];
    const float* w_k1  = (const float*)d_in[5];  const float* b_k1 = (const float*)d_in[6];
    const float* w_q1  = (const float*)d_in[7];  const float* b_q1 = (const float*)d_in[8];
    const float* w_k2  = (const float*)d_in[9];  const float* b_k2 = (const float*)d_in[10];
    const float* w_q2  = (const float*)d_in[11]; const float* b_q2 = (const float*)d_in[12];
    const float* w_ts  = (const float*)d_in[13]; const float* b_ts = (const float*)d_in[14];
    const float* gts   = (const float*)d_in[15]; const float* bets = (const float*)d_in[16];
    const float* mts   = (const float*)d_in[17]; const float* vts  = (const float*)d_in[18];
    const float* w_tq  = (const float*)d_in[19]; const float* b_tq = (const float*)d_in[20];
    const float* gtq   = (const float*)d_in[21]; const float* betq = (const float*)d_in[22];
    const float* mtq   = (const float*)d_in[23]; const float* vtq  = (const float*)d_in[24];
    const float* w_cat = (const float*)d_in[25];
    const float* gcat  = (const float*)d_in[26]; const float* becat= (const float*)d_in[27];
    const float* mcat  = (const float*)d_in[28]; const float* vcat = (const float*)d_in[29];

    float* out  = (float*)d_out;
    float* cpam = out;                                   // [2,128,64,64]
    float* Eq   = out + (size_t)NB * CI * NPIX;          // [2,128,64,64]
    float* Es   = out + 2 * (size_t)NB * CI * NPIX;      // [2,128,64,64]

    dim3 g32(32, NB);
    // values / keys / queries / transform branches
    conv1x1_kernel<128, false><<<g32, 256>>>(q, w_v,  b_v,  nullptr, nullptr, nullptr, nullptr, 0, 0);
    conv1x1_kernel<128, false><<<g32, 256>>>(s, w_v,  b_v,  nullptr, nullptr, nullptr, nullptr, 1, 0);
    conv1x1_kernel< 64, false><<<g32, 256>>>(q, w_k1, b_k1, nullptr, nullptr, nullptr, nullptr, 2, 0);
    conv1x1_kernel< 64, false><<<g32, 256>>>(s, w_k2, b_k2, nullptr, nullptr, nullptr, nullptr, 2, 64);
    conv1x1_kernel< 64, false><<<g32, 256>>>(q, w_q1, b_q1, nullptr, nullptr, nullptr, nullptr, 3, 0);
    conv1x1_kernel< 64, false><<<g32, 256>>>(s, w_q2, b_q2, nullptr, nullptr, nullptr, nullptr, 3, 64);
    conv1x1_kernel<128, true ><<<g32, 256>>>(s, w_ts, b_ts, gts, bets, mts, vts, 4, 0);
    conv1x1_kernel<128, true ><<<g32, 256>>>(q, w_tq, b_tq, gtq, betq, mtq, vtq, 5, 0);

    gemmA_kernel<<<dim3(32, 32, NB), 256>>>();

    rowstats_kernel<<<dim3(NPIX, NB), 256>>>();
    colstats_partial_kernel<<<dim3(16, 8, NB), 256>>>();
    colstats_combine_kernel<<<(NB * NPIX) / 256, 256>>>();

    pv_kernel<<<dim3(32, NB, 2), 256>>>(scale, Eq, Es);

    conv3x3_kernel<<<dim3(64, NB), 256>>>(w_cat, gcat, becat, mcat, vcat, Eq, Es, cpam);
}